// round 1
// baseline (speedup 1.0000x reference)
#include <cuda_runtime.h>
#include <cstdint>
#include <math.h>

#define BATCH 64
#define SEQ   512
#define EMBD  128
#define HID   256
#define TAGS  9
#define G4    1024            // 4*HID
#define NROWS (BATCH*SEQ)     // 32768
#define LOGITS_N (NROWS*TAGS) // 294912

// ---------------- scratch (static device allocations are allowed) ----------
__device__ float g_xz[2ull*NROWS*G4];          // 256MB: pre-activations per dir
__device__ float g_h[(size_t)NROWS*2*HID];     // 64MB:  concat [fwd|bwd] hidden
__device__ int   g_lens[BATCH];

__device__ __forceinline__ float sigf(float x){ return 1.f/(1.f+__expf(-x)); }
__device__ __forceinline__ float tnh (float x){ return 1.f - 2.f/(__expf(2.f*x)+1.f); }

// ---------------- lens ------------------------------------------------------
__global__ void lens_kernel(const int* __restrict__ text, float* __restrict__ out_lens)
{
    int b = blockIdx.x;
    int cnt = 0;
    for (int s = threadIdx.x; s < SEQ; s += blockDim.x)
        cnt += (text[b*SEQ + s] != 0);
    for (int o = 16; o; o >>= 1) cnt += __shfl_down_sync(0xffffffffu, cnt, o);
    __shared__ int ws[4];
    if ((threadIdx.x & 31) == 0) ws[threadIdx.x >> 5] = cnt;
    __syncthreads();
    if (threadIdx.x == 0) {
        int t = ws[0] + ws[1] + ws[2] + ws[3];
        g_lens[b] = t;
        out_lens[b] = (float)t;
    }
}

// ---------------- fused embedding gather + input projection ----------------
// out[d][row][col] = emb[text[row]] @ W_d + b_d, row = b*SEQ+s, col in [0,1024)
// grid: (8 colblocks, 512 rowblocks, 2 dirs), 256 threads
__global__ void __launch_bounds__(256)
inproj_kernel(const int* __restrict__ text, const float* __restrict__ emb,
              const float* __restrict__ W_f, const float* __restrict__ W_b,
              const float* __restrict__ b_f, const float* __restrict__ b_b)
{
    extern __shared__ float sm[];
    float* As = sm;              // [64][128]
    float* Bs = sm + 64*128;     // [128][128]

    const int nb = blockIdx.x, mb = blockIdx.y, d = blockIdx.z;
    const int tid = threadIdx.x;
    const int row0 = mb*64;
    const int col0 = nb*128;
    const float* W    = d ? W_b : W_f;
    const float* bias = d ? b_b : b_f;

    for (int i = tid; i < 64*128; i += 256) {
        int r = i >> 7, k = i & 127;
        int tok = text[row0 + r];
        As[i] = emb[(size_t)tok*EMBD + k];
    }
    for (int i = tid; i < 128*128; i += 256) {
        int k = i >> 7, cc = i & 127;
        Bs[i] = W[(size_t)k*G4 + col0 + cc];
    }
    __syncthreads();

    const int ty = tid >> 5, tx = tid & 31;  // warp owns 8 rows; lane owns 4 cols
    float acc[8][4];
    #pragma unroll
    for (int j = 0; j < 8; j++)
        acc[j][0] = acc[j][1] = acc[j][2] = acc[j][3] = 0.f;

    const float4* Bs4 = (const float4*)Bs;
    #pragma unroll 4
    for (int k = 0; k < 128; k++) {
        float4 b4 = Bs4[k*32 + tx];
        #pragma unroll
        for (int j = 0; j < 8; j++) {
            float a = As[(ty*8 + j)*128 + k];   // warp-uniform broadcast
            acc[j][0] = fmaf(a, b4.x, acc[j][0]);
            acc[j][1] = fmaf(a, b4.y, acc[j][1]);
            acc[j][2] = fmaf(a, b4.z, acc[j][2]);
            acc[j][3] = fmaf(a, b4.w, acc[j][3]);
        }
    }
    float4 bb = *(const float4*)(bias + col0 + tx*4);
    float* outp = g_xz + (size_t)d*NROWS*G4;
    #pragma unroll
    for (int j = 0; j < 8; j++) {
        float4 v = make_float4(acc[j][0]+bb.x, acc[j][1]+bb.y,
                               acc[j][2]+bb.z, acc[j][3]+bb.w);
        *(float4*)(outp + (size_t)(row0 + ty*8 + j)*G4 + col0 + tx*4) = v;
    }
}

// ---------------- LSTM scan: persistent-U cluster kernel -------------------
// grid (8,8,2): x = hidden-group (cluster dim), y = batch-group(8 batches), z = dir
// Each CTA: U slice [256 k][128 cols = 4 gates x 32 hidden] resident in SMEM.
// Per step: z = xz + h@Uslice; gate update for its 32 hidden; broadcast h slice
// to 8 cluster CTAs via DSMEM; one cluster barrier (double-buffered h).
#define CLUSTER_BAR() do { \
    asm volatile("barrier.cluster.arrive.aligned;" ::: "memory"); \
    asm volatile("barrier.cluster.wait.aligned;"   ::: "memory"); \
} while (0)

__global__ void __cluster_dims__(8,1,1) __launch_bounds__(256,1)
lstm_kernel(const float* __restrict__ Uf, const float* __restrict__ Ub)
{
    extern __shared__ float sm[];
    float* Us   = sm;                  // [256][128]        128KB
    float* hbuf = sm + 256*128;        // [2][8][256]       16KB (double buffer)
    float* zs   = hbuf + 2*8*HID;      // [8][128]          4KB

    const int c   = blockIdx.x;        // hidden group (cluster rank)
    const int g   = blockIdx.y;        // batch group
    const int d   = blockIdx.z;        // direction
    const int tid = threadIdx.x;
    const float* U = d ? Ub : Uf;

    // load U slice: local col lc = q*32+jj  ->  global col q*256 + c*32 + jj
    for (int i = tid; i < 256*128; i += 256) {
        int k = i >> 7, lc = i & 127;
        int q = lc >> 5, jj = lc & 31;
        Us[i] = U[(size_t)k*G4 + q*HID + c*32 + jj];
    }
    for (int i = tid; i < 8*HID; i += 256) hbuf[i] = 0.f;   // h0 = 0 (buffer 0)
    __syncthreads();
    CLUSTER_BAR();   // peers must not write our hbuf[1] before init is done

    // compute-phase mapping: thread = (local batch b, col quad colq)
    const int b    = tid >> 5;
    const int colq = tid & 31;
    const int q    = colq >> 3;
    const int jj0  = (colq & 7)*4;
    const int gcol = q*HID + c*32 + jj0;        // global xz column base
    const int bg   = g*8 + b;
    const float* xzbase = g_xz + (size_t)d*NROWS*G4;

    // gate-phase mapping (threads 0..63): thread = (batch gb, hidden quad gj0)
    const int gb  = tid >> 3;
    const int gj0 = (tid & 7)*4;
    float4 cs = make_float4(0.f, 0.f, 0.f, 0.f);  // c state, register-resident

    uint32_t hbuf_u32;
    asm("{ .reg .u64 ta; cvta.to.shared.u64 ta, %1; cvt.u32.u64 %0, ta; }"
        : "=r"(hbuf_u32) : "l"(hbuf));

    const float4* Us4 = (const float4*)Us;
    int p = 0;
    for (int s = 0; s < SEQ; s++) {
        const int t = d ? (SEQ - 1 - s) : s;
        const float* xzr = xzbase + ((size_t)bg*SEQ + t)*G4;
        float4 acc = *(const float4*)(xzr + gcol);

        const float4* hb4 = (const float4*)(hbuf + p*(8*HID) + b*HID);
        #pragma unroll 8
        for (int k4 = 0; k4 < 64; k4++) {
            float4 h4 = hb4[k4];                       // warp-wide broadcast
            float4 u;
            u = Us4[(k4*4+0)*32 + colq];
            acc.x = fmaf(h4.x,u.x,acc.x); acc.y = fmaf(h4.x,u.y,acc.y);
            acc.z = fmaf(h4.x,u.z,acc.z); acc.w = fmaf(h4.x,u.w,acc.w);
            u = Us4[(k4*4+1)*32 + colq];
            acc.x = fmaf(h4.y,u.x,acc.x); acc.y = fmaf(h4.y,u.y,acc.y);
            acc.z = fmaf(h4.y,u.z,acc.z); acc.w = fmaf(h4.y,u.w,acc.w);
            u = Us4[(k4*4+2)*32 + colq];
            acc.x = fmaf(h4.z,u.x,acc.x); acc.y = fmaf(h4.z,u.y,acc.y);
            acc.z = fmaf(h4.z,u.z,acc.z); acc.w = fmaf(h4.z,u.w,acc.w);
            u = Us4[(k4*4+3)*32 + colq];
            acc.x = fmaf(h4.w,u.x,acc.x); acc.y = fmaf(h4.w,u.y,acc.y);
            acc.z = fmaf(h4.w,u.z,acc.z); acc.w = fmaf(h4.w,u.w,acc.w);
        }
        ((float4*)zs)[b*32 + colq] = acc;
        __syncthreads();

        if (tid < 64) {
            const float4* z4 = (const float4*)(zs + gb*128);
            float4 iv = z4[ 0 + (gj0>>2)];
            float4 fv = z4[ 8 + (gj0>>2)];
            float4 gv = z4[16 + (gj0>>2)];
            float4 ov = z4[24 + (gj0>>2)];
            cs.x = sigf(fv.x)*cs.x + sigf(iv.x)*tnh(gv.x);
            cs.y = sigf(fv.y)*cs.y + sigf(iv.y)*tnh(gv.y);
            cs.z = sigf(fv.z)*cs.z + sigf(iv.z)*tnh(gv.z);
            cs.w = sigf(fv.w)*cs.w + sigf(iv.w)*tnh(gv.w);
            float4 hv;
            hv.x = sigf(ov.x)*tnh(cs.x);
            hv.y = sigf(ov.y)*tnh(cs.y);
            hv.z = sigf(ov.z)*tnh(cs.z);
            hv.w = sigf(ov.w)*tnh(cs.w);

            // h out (concat layout [b][t][ fwd 0:256 | bwd 256:512 ])
            *(float4*)(g_h + ((size_t)(g*8+gb)*SEQ + t)*(2*HID) + d*HID + c*32 + gj0) = hv;

            // broadcast h slice into next buffer of all 8 cluster CTAs
            uint32_t laddr = hbuf_u32 +
                (uint32_t)(((1-p)*(8*HID) + gb*HID + c*32 + gj0)*4);
            #pragma unroll
            for (int r = 0; r < 8; r++) {
                uint32_t raddr;
                asm volatile("mapa.shared::cluster.u32 %0, %1, %2;"
                             : "=r"(raddr) : "r"(laddr), "r"(r));
                asm volatile("st.shared::cluster.v4.f32 [%0], {%1,%2,%3,%4};"
                             :: "r"(raddr), "f"(hv.x), "f"(hv.y), "f"(hv.z), "f"(hv.w)
                             : "memory");
            }
        }
        CLUSTER_BAR();   // release writes / acquire peers' writes; also CTA sync
        p ^= 1;
    }
}

// ---------------- logits = h @ W_d + b_d  (warp per row) -------------------
__global__ void __launch_bounds__(256)
logits_kernel(const float* __restrict__ Wd, const float* __restrict__ bd,
              float* __restrict__ out)
{
    __shared__ float Ws[2*HID*TAGS];   // 18KB
    const int tid = threadIdx.x;
    for (int i = tid; i < 2*HID*TAGS; i += 256) Ws[i] = Wd[i];
    __syncthreads();

    const int warp = tid >> 5, lane = tid & 31;
    const int row = blockIdx.x*8 + warp;
    const float* hr = g_h + (size_t)row*(2*HID);

    float a[TAGS];
    #pragma unroll
    for (int tg = 0; tg < TAGS; tg++) a[tg] = 0.f;
    for (int k = lane; k < 2*HID; k += 32) {
        float hv = hr[k];
        #pragma unroll
        for (int tg = 0; tg < TAGS; tg++) a[tg] = fmaf(hv, Ws[k*TAGS + tg], a[tg]);
    }
    #pragma unroll
    for (int tg = 0; tg < TAGS; tg++)
        for (int o = 16; o; o >>= 1) a[tg] += __shfl_down_sync(0xffffffffu, a[tg], o);
    if (lane == 0) {
        #pragma unroll
        for (int tg = 0; tg < TAGS; tg++)
            out[(size_t)row*TAGS + tg] = a[tg] + bd[tg];
    }
}

// ---------------- CRF: forward log-norm + sequence score (warp per batch) --
__global__ void crf_kernel(const int* __restrict__ labels, const float* __restrict__ trans,
                           const float* __restrict__ logits, float* __restrict__ out_ll)
{
    __shared__ float tr[TAGS*TAGS];
    __shared__ float alpha[TAGS];
    const int b = blockIdx.x;
    const int tid = threadIdx.x;   // 32 threads

    for (int i = tid; i < TAGS*TAGS; i += 32) tr[i] = trans[i];
    const int len = g_lens[b];
    const float* lg = logits + (size_t)b*SEQ*TAGS;
    if (tid < TAGS) alpha[tid] = lg[tid];
    __syncwarp();

    for (int t = 1; t < len; t++) {
        float nv = 0.f;
        if (tid < TAGS) {
            float m = -1e30f;
            #pragma unroll
            for (int i = 0; i < TAGS; i++) m = fmaxf(m, alpha[i] + tr[i*TAGS + tid]);
            float s = 0.f;
            #pragma unroll
            for (int i = 0; i < TAGS; i++) s += __expf(alpha[i] + tr[i*TAGS + tid] - m);
            nv = m + __logf(s) + lg[t*TAGS + tid];
        }
        __syncwarp();
        if (tid < TAGS) alpha[tid] = nv;
        __syncwarp();
    }

    // sequence score (unary + binary), warp-strided
    const int* lb = labels + b*SEQ;
    float sc = 0.f;
    for (int t = tid; t < len; t += 32)      sc += lg[t*TAGS + lb[t]];
    for (int t = tid; t + 1 < len; t += 32)  sc += tr[lb[t]*TAGS + lb[t+1]];
    for (int o = 16; o; o >>= 1) sc += __shfl_down_sync(0xffffffffu, sc, o);

    if (tid == 0) {
        float m = -1e30f;
        #pragma unroll
        for (int i = 0; i < TAGS; i++) m = fmaxf(m, alpha[i]);
        float s = 0.f;
        #pragma unroll
        for (int i = 0; i < TAGS; i++) s += __expf(alpha[i] - m);
        out_ll[b] = sc - (m + __logf(s));
    }
}

// ---------------- launch ----------------------------------------------------
extern "C" void kernel_launch(void* const* d_in, const int* in_sizes, int n_in,
                              void* d_out, int out_size)
{
    (void)in_sizes; (void)n_in; (void)out_size;
    const int*   text   = (const int*)  d_in[0];
    const int*   labels = (const int*)  d_in[1];
    const float* emb    = (const float*)d_in[2];
    const float* W_f    = (const float*)d_in[3];
    const float* U_f    = (const float*)d_in[4];
    const float* b_f    = (const float*)d_in[5];
    const float* W_b    = (const float*)d_in[6];
    const float* U_b    = (const float*)d_in[7];
    const float* b_b    = (const float*)d_in[8];
    const float* W_d    = (const float*)d_in[9];
    const float* b_d    = (const float*)d_in[10];
    const float* trans  = (const float*)d_in[11];
    float* out = (float*)d_out;

    const int gemm_smem = (64*128 + 128*128) * 4;            // 98304
    const int lstm_smem = (256*128 + 2*8*HID + 8*128) * 4;   // 151552
    cudaFuncSetAttribute(inproj_kernel, cudaFuncAttributeMaxDynamicSharedMemorySize, gemm_smem);
    cudaFuncSetAttribute(lstm_kernel,   cudaFuncAttributeMaxDynamicSharedMemorySize, lstm_smem);

    lens_kernel<<<BATCH, 128>>>(text, out + LOGITS_N);

    dim3 ggrid(8, NROWS/64, 2);
    inproj_kernel<<<ggrid, 256, gemm_smem>>>(text, emb, W_f, W_b, b_f, b_b);

    dim3 lgrid(8, 8, 2);
    lstm_kernel<<<lgrid, 256, lstm_smem>>>(U_f, U_b);

    logits_kernel<<<NROWS/8, 256>>>(W_d, b_d, out);

    crf_kernel<<<BATCH, 32>>>(labels, trans, out, out + LOGITS_N + BATCH);
}

// round 2
// speedup vs baseline: 1.9298x; 1.9298x over previous
#include <cuda_runtime.h>
#include <cstdint>
#include <math.h>

#define BATCH 64
#define SEQ   512
#define EMBD  128
#define HID   256
#define TAGS  9
#define G4    1024            // 4*HID
#define NROWS (BATCH*SEQ)     // 32768
#define LOGITS_N (NROWS*TAGS) // 294912

typedef unsigned long long ull;

// ---------------- scratch ---------------------------------------------------
__device__ float g_xz[2ull*NROWS*G4];          // 256MB: pre-activations per dir
__device__ float g_h[(size_t)NROWS*2*HID];     // 64MB:  concat [fwd|bwd] hidden
__device__ int   g_lens[BATCH];

__device__ __forceinline__ float sigf(float x){ return 1.f/(1.f+__expf(-x)); }
__device__ __forceinline__ float tnh (float x){ return 1.f - 2.f/(__expf(2.f*x)+1.f); }

// packed fp32x2 helpers (Blackwell FFMA2)
__device__ __forceinline__ ull pack2(float x){
    ull r; unsigned u = __float_as_uint(x);
    asm("mov.b64 %0, {%1,%1};" : "=l"(r) : "r"(u));
    return r;
}
__device__ __forceinline__ ull packab(float a, float b){
    ull r;
    asm("mov.b64 %0, {%1,%2};" : "=l"(r) : "r"(__float_as_uint(a)), "r"(__float_as_uint(b)));
    return r;
}
__device__ __forceinline__ void fma2(ull &a, ull h, ull u){
    asm("fma.rn.f32x2 %0, %1, %2, %0;" : "+l"(a) : "l"(h), "l"(u));
}
__device__ __forceinline__ float2 unpack2(ull v){
    unsigned lo, hi;
    asm("mov.b64 {%0,%1}, %2;" : "=r"(lo), "=r"(hi) : "l"(v));
    return make_float2(__uint_as_float(lo), __uint_as_float(hi));
}

// ---------------- lens ------------------------------------------------------
__global__ void lens_kernel(const int* __restrict__ text, float* __restrict__ out_lens)
{
    int b = blockIdx.x;
    int cnt = 0;
    for (int s = threadIdx.x; s < SEQ; s += blockDim.x)
        cnt += (text[b*SEQ + s] != 0);
    for (int o = 16; o; o >>= 1) cnt += __shfl_down_sync(0xffffffffu, cnt, o);
    __shared__ int ws[4];
    if ((threadIdx.x & 31) == 0) ws[threadIdx.x >> 5] = cnt;
    __syncthreads();
    if (threadIdx.x == 0) {
        int t = ws[0] + ws[1] + ws[2] + ws[3];
        g_lens[b] = t;
        out_lens[b] = (float)t;
    }
}

// ---------------- fused embedding gather + input projection ----------------
// f32x2 inner loop; As stored transposed [k][row(+pad)] so a-values come from
// 2 broadcast LDS.128 per k; B cols packed natively as ulonglong2.
#define AS_STRIDE 68   // 64 rows + pad; 68*4B = 272 = 16-aligned rows
__global__ void __launch_bounds__(256)
inproj_kernel(const int* __restrict__ text, const float* __restrict__ emb,
              const float* __restrict__ W_f, const float* __restrict__ W_b,
              const float* __restrict__ b_f, const float* __restrict__ b_b)
{
    extern __shared__ float sm[];
    float* As = sm;                     // [128 k][AS_STRIDE]
    float* Bs = sm + 128*AS_STRIDE;     // [128 k][128 cols]

    const int nb = blockIdx.x, mb = blockIdx.y, d = blockIdx.z;
    const int tid = threadIdx.x;
    const int row0 = mb*64;
    const int col0 = nb*128;
    const float* W    = d ? W_b : W_f;
    const float* bias = d ? b_b : b_f;

    for (int i = tid; i < 64*128; i += 256) {
        int r = i >> 7, k = i & 127;
        int tok = text[row0 + r];
        As[k*AS_STRIDE + r] = emb[(size_t)tok*EMBD + k];
    }
    for (int i = tid; i < 128*128; i += 256) {
        int k = i >> 7, cc = i & 127;
        Bs[i] = W[(size_t)k*G4 + col0 + cc];
    }
    __syncthreads();

    const int ty = tid >> 5, tx = tid & 31;  // warp owns 8 rows; lane owns 4 cols
    ull acc[8][2];
    #pragma unroll
    for (int j = 0; j < 8; j++) acc[j][0] = acc[j][1] = 0ULL;

    const ulonglong2* Bs2 = (const ulonglong2*)Bs;
    #pragma unroll 4
    for (int k = 0; k < 128; k++) {
        ulonglong2 bp = Bs2[k*32 + tx];                       // cols 4tx..4tx+3 packed
        float4 a0 = *(const float4*)(As + k*AS_STRIDE + ty*8);     // rows, broadcast
        float4 a1 = *(const float4*)(As + k*AS_STRIDE + ty*8 + 4);
        ull ad;
        ad = pack2(a0.x); fma2(acc[0][0], ad, bp.x); fma2(acc[0][1], ad, bp.y);
        ad = pack2(a0.y); fma2(acc[1][0], ad, bp.x); fma2(acc[1][1], ad, bp.y);
        ad = pack2(a0.z); fma2(acc[2][0], ad, bp.x); fma2(acc[2][1], ad, bp.y);
        ad = pack2(a0.w); fma2(acc[3][0], ad, bp.x); fma2(acc[3][1], ad, bp.y);
        ad = pack2(a1.x); fma2(acc[4][0], ad, bp.x); fma2(acc[4][1], ad, bp.y);
        ad = pack2(a1.y); fma2(acc[5][0], ad, bp.x); fma2(acc[5][1], ad, bp.y);
        ad = pack2(a1.z); fma2(acc[6][0], ad, bp.x); fma2(acc[6][1], ad, bp.y);
        ad = pack2(a1.w); fma2(acc[7][0], ad, bp.x); fma2(acc[7][1], ad, bp.y);
    }
    float4 bb = *(const float4*)(bias + col0 + tx*4);
    float* outp = g_xz + (size_t)d*NROWS*G4;
    #pragma unroll
    for (int j = 0; j < 8; j++) {
        float2 lo = unpack2(acc[j][0]);
        float2 hi = unpack2(acc[j][1]);
        float4 v = make_float4(lo.x+bb.x, lo.y+bb.y, hi.x+bb.z, hi.y+bb.w);
        *(float4*)(outp + (size_t)(row0 + ty*8 + j)*G4 + col0 + tx*4) = v;
    }
}

// ---------------- LSTM scan: persistent-U cluster kernel (v2) --------------
// grid (8,8,2): x = hidden-group (cluster dim), y = batch-group, z = dir.
// FMA phase: warp w -> (kq = w>>1 : 64-k quarter, cg = w&1 : 64-col half);
//   lane owns a col pair; 8 batches packed as 4 f32x2 accumulators per col.
//   U read ONCE per step (128KB -> 1024 crossbar cyc); h via 2 bcast LDS per k.
// Gate phase: all 256 threads, thread = (b = tid&7, hid = tid>>3); sums the
//   4 k-split partials + xz (prefetched LDG), applies gates, broadcasts the
//   packed (b,b+1) h-pair to all 8 cluster CTAs via DSMEM.
#define ZS_STRIDE 132   // f32x2 units per partial row; conflict-free gate reads
#define CLUSTER_BAR() do { \
    asm volatile("barrier.cluster.arrive.aligned;" ::: "memory"); \
    asm volatile("barrier.cluster.wait.aligned;"   ::: "memory"); \
} while (0)

__global__ void __cluster_dims__(8,1,1) __launch_bounds__(256,1)
lstm_kernel(const float* __restrict__ Uf, const float* __restrict__ Ub)
{
    extern __shared__ float sm[];
    float* Us  = sm;                         // [256 k][128 lc]      131072 B
    ull*   hb2 = (ull*)(sm + 256*128);       // [2][256 k][4 bpair]   16384 B
    ull*   zs2 = hb2 + 2*256*4;              // [16 row][ZS_STRIDE]   16896 B

    const int c   = blockIdx.x;        // hidden group (cluster rank)
    const int g   = blockIdx.y;        // batch group
    const int d   = blockIdx.z;        // direction
    const int tid = threadIdx.x;
    const float* U = d ? Ub : Uf;

    // U slice: local col lc = q*32+jj  ->  global col q*256 + c*32 + jj
    for (int i = tid; i < 256*128; i += 256) {
        int k = i >> 7, lc = i & 127;
        int q = lc >> 5, jj = lc & 31;
        Us[i] = U[(size_t)k*G4 + q*HID + c*32 + jj];
    }
    for (int i = tid; i < 256*4; i += 256) hb2[i] = 0ULL;   // h0 = 0 (buffer 0)
    __syncthreads();
    CLUSTER_BAR();

    // FMA-phase mapping
    const int w    = tid >> 5, lane = tid & 31;
    const int kq   = w >> 1;           // k quarter: [kq*64, kq*64+64)
    const int cg   = w & 1;            // col half
    const int lc0  = cg*64 + lane*2;   // local col pair (lc0, lc0+1)

    // gate-phase mapping
    const int b   = tid & 7;
    const int hid = tid >> 3;          // 0..31 local hidden
    const int bg  = g*8 + b;
    const float* xzb = g_xz + (size_t)d*NROWS*G4 + (size_t)bg*SEQ*G4 + c*32 + hid;
    float cstate = 0.f;

    uint32_t hb2_u32;
    asm("{ .reg .u64 ta; cvta.to.shared.u64 ta, %1; cvt.u32.u64 %0, ta; }"
        : "=r"(hb2_u32) : "l"(hb2));

    int p = 0;
    for (int s = 0; s < SEQ; s++) {
        const int t = d ? (SEQ - 1 - s) : s;
        // prefetch xz gate inputs (consumed after the FMA loop + sync)
        const float* xzr = xzb + (size_t)t*G4;
        float xz0 = __ldg(xzr);
        float xz1 = __ldg(xzr + 256);
        float xz2 = __ldg(xzr + 512);
        float xz3 = __ldg(xzr + 768);

        // ---- h @ U partial (this warp's k quarter, col pair) ----
        ull acc[4][2];
        #pragma unroll
        for (int pp = 0; pp < 4; pp++) acc[pp][0] = acc[pp][1] = 0ULL;

        const ull* hrow = hb2 + (size_t)p*1024 + (size_t)kq*64*4;
        const float* Uk = Us + kq*64*128 + lc0;
        #pragma unroll 4
        for (int kk = 0; kk < 64; kk++) {
            float2 u = *(const float2*)(Uk + kk*128);
            ull u0 = pack2(u.x), u1 = pack2(u.y);
            ulonglong2 hA = *(const ulonglong2*)(hrow + kk*4);      // pairs 0,1
            ulonglong2 hB = *(const ulonglong2*)(hrow + kk*4 + 2);  // pairs 2,3
            fma2(acc[0][0], hA.x, u0); fma2(acc[0][1], hA.x, u1);
            fma2(acc[1][0], hA.y, u0); fma2(acc[1][1], hA.y, u1);
            fma2(acc[2][0], hB.x, u0); fma2(acc[2][1], hB.x, u1);
            fma2(acc[3][0], hB.y, u0); fma2(acc[3][1], hB.y, u1);
        }
        #pragma unroll
        for (int pp = 0; pp < 4; pp++) {
            *(ulonglong2*)(zs2 + (size_t)(kq*4 + pp)*ZS_STRIDE + lc0) =
                make_ulonglong2(acc[pp][0], acc[pp][1]);
        }
        __syncthreads();

        // ---- gates: sum 4 k-partials + xz, nonlinearity ----
        float zsum[4];
        #pragma unroll
        for (int q = 0; q < 4; q++) {
            float ssum = (q==0) ? xz0 : (q==1) ? xz1 : (q==2) ? xz2 : xz3;
            #pragma unroll
            for (int k2 = 0; k2 < 4; k2++) {
                const float* zp = (const float*)(zs2 + (size_t)(k2*4 + (b>>1))*ZS_STRIDE
                                                 + q*32 + hid) + (b & 1);
                ssum += *zp;
            }
            zsum[q] = ssum;
        }
        cstate = sigf(zsum[1])*cstate + sigf(zsum[0])*tnh(zsum[2]);
        float hv = sigf(zsum[3])*tnh(cstate);

        g_h[((size_t)bg*SEQ + t)*(2*HID) + d*HID + c*32 + hid] = hv;

        // pack (even b, odd b) pair and broadcast to all 8 cluster CTAs
        float hpart = __shfl_xor_sync(0xffffffffu, hv, 1);
        if (!(b & 1)) {
            ull pairv = packab(hv, hpart);
            uint32_t laddr = hb2_u32 +
                (uint32_t)((((1 - p)*256 + c*32 + hid)*4 + (b >> 1)) * 8);
            #pragma unroll
            for (int r = 0; r < 8; r++) {
                uint32_t raddr;
                asm volatile("mapa.shared::cluster.u32 %0, %1, %2;"
                             : "=r"(raddr) : "r"(laddr), "r"(r));
                asm volatile("st.shared::cluster.b64 [%0], %1;"
                             :: "r"(raddr), "l"(pairv) : "memory");
            }
        }
        CLUSTER_BAR();   // release DSMEM writes, full CTA+cluster sync
        p ^= 1;
    }
}

// ---------------- logits = h @ W_d + b_d  (warp per row) -------------------
__global__ void __launch_bounds__(256)
logits_kernel(const float* __restrict__ Wd, const float* __restrict__ bd,
              float* __restrict__ out)
{
    __shared__ float Ws[2*HID*TAGS];   // 18KB
    const int tid = threadIdx.x;
    for (int i = tid; i < 2*HID*TAGS; i += 256) Ws[i] = Wd[i];
    __syncthreads();

    const int warp = tid >> 5, lane = tid & 31;
    const int row = blockIdx.x*8 + warp;
    const float* hr = g_h + (size_t)row*(2*HID);

    float a[TAGS];
    #pragma unroll
    for (int tg = 0; tg < TAGS; tg++) a[tg] = 0.f;
    for (int k = lane; k < 2*HID; k += 32) {
        float hv = hr[k];
        #pragma unroll
        for (int tg = 0; tg < TAGS; tg++) a[tg] = fmaf(hv, Ws[k*TAGS + tg], a[tg]);
    }
    #pragma unroll
    for (int tg = 0; tg < TAGS; tg++)
        for (int o = 16; o; o >>= 1) a[tg] += __shfl_down_sync(0xffffffffu, a[tg], o);
    if (lane == 0) {
        #pragma unroll
        for (int tg = 0; tg < TAGS; tg++)
            out[(size_t)row*TAGS + tg] = a[tg] + bd[tg];
    }
}

// ---------------- CRF: forward log-norm + sequence score (warp per batch) --
__global__ void crf_kernel(const int* __restrict__ labels, const float* __restrict__ trans,
                           const float* __restrict__ logits, float* __restrict__ out_ll)
{
    __shared__ float tr[TAGS*TAGS];
    __shared__ float alpha[TAGS];
    const int b = blockIdx.x;
    const int tid = threadIdx.x;   // 32 threads

    for (int i = tid; i < TAGS*TAGS; i += 32) tr[i] = trans[i];
    const int len = g_lens[b];
    const float* lg = logits + (size_t)b*SEQ*TAGS;
    if (tid < TAGS) alpha[tid] = lg[tid];
    __syncwarp();

    for (int t = 1; t < len; t++) {
        float nv = 0.f;
        if (tid < TAGS) {
            float m = -1e30f;
            #pragma unroll
            for (int i = 0; i < TAGS; i++) m = fmaxf(m, alpha[i] + tr[i*TAGS + tid]);
            float s = 0.f;
            #pragma unroll
            for (int i = 0; i < TAGS; i++) s += __expf(alpha[i] + tr[i*TAGS + tid] - m);
            nv = m + __logf(s) + lg[t*TAGS + tid];
        }
        __syncwarp();
        if (tid < TAGS) alpha[tid] = nv;
        __syncwarp();
    }

    const int* lb = labels + b*SEQ;
    float sc = 0.f;
    for (int t = tid; t < len; t += 32)      sc += lg[t*TAGS + lb[t]];
    for (int t = tid; t + 1 < len; t += 32)  sc += tr[lb[t]*TAGS + lb[t+1]];
    for (int o = 16; o; o >>= 1) sc += __shfl_down_sync(0xffffffffu, sc, o);

    if (tid == 0) {
        float m = -1e30f;
        #pragma unroll
        for (int i = 0; i < TAGS; i++) m = fmaxf(m, alpha[i]);
        float s = 0.f;
        #pragma unroll
        for (int i = 0; i < TAGS; i++) s += __expf(alpha[i] - m);
        out_ll[b] = sc - (m + __logf(s));
    }
}

// ---------------- launch ----------------------------------------------------
extern "C" void kernel_launch(void* const* d_in, const int* in_sizes, int n_in,
                              void* d_out, int out_size)
{
    (void)in_sizes; (void)n_in; (void)out_size;
    const int*   text   = (const int*)  d_in[0];
    const int*   labels = (const int*)  d_in[1];
    const float* emb    = (const float*)d_in[2];
    const float* W_f    = (const float*)d_in[3];
    const float* U_f    = (const float*)d_in[4];
    const float* b_f    = (const float*)d_in[5];
    const float* W_b    = (const float*)d_in[6];
    const float* U_b    = (const float*)d_in[7];
    const float* b_b    = (const float*)d_in[8];
    const float* W_d    = (const float*)d_in[9];
    const float* b_d    = (const float*)d_in[10];
    const float* trans  = (const float*)d_in[11];
    float* out = (float*)d_out;

    const int gemm_smem = (128*AS_STRIDE + 128*128) * 4;            // 100352
    const int lstm_smem = 256*128*4 + 2*256*4*8 + 16*ZS_STRIDE*8;   // 164352
    cudaFuncSetAttribute(inproj_kernel, cudaFuncAttributeMaxDynamicSharedMemorySize, gemm_smem);
    cudaFuncSetAttribute(lstm_kernel,   cudaFuncAttributeMaxDynamicSharedMemorySize, lstm_smem);

    lens_kernel<<<BATCH, 128>>>(text, out + LOGITS_N);

    dim3 ggrid(8, NROWS/64, 2);
    inproj_kernel<<<ggrid, 256, gemm_smem>>>(text, emb, W_f, W_b, b_f, b_b);

    dim3 lgrid(8, 8, 2);
    lstm_kernel<<<lgrid, 256, lstm_smem>>>(U_f, U_b);

    logits_kernel<<<NROWS/8, 256>>>(W_d, b_d, out);

    crf_kernel<<<BATCH, 32>>>(labels, trans, out, out + LOGITS_N + BATCH);
}

// round 6
// speedup vs baseline: 2.3608x; 1.2234x over previous
#include <cuda_runtime.h>
#include <cstdint>
#include <math.h>

#define BATCH 64
#define SEQ   512
#define EMBD  128
#define HID   256
#define TAGS  9
#define G4    1024            // 4*HID
#define NROWS (BATCH*SEQ)     // 32768
#define LOGITS_N (NROWS*TAGS) // 294912

typedef unsigned long long ull;

// ---------------- scratch ---------------------------------------------------
__device__ float g_xz[2ull*NROWS*G4];          // 256MB: pre-activations per dir
__device__ float g_h[(size_t)NROWS*2*HID];     // 64MB:  concat [fwd|bwd] hidden
__device__ int   g_lens[BATCH];

__device__ __forceinline__ float sigf(float x){ return 1.f/(1.f+__expf(-x)); }
__device__ __forceinline__ float tnh (float x){ return 1.f - 2.f/(__expf(2.f*x)+1.f); }

// fast HW tanh (MUFU.TANH) + sigmoid via tanh
__device__ __forceinline__ float tanh_a(float x){
    float y; asm("tanh.approx.f32 %0, %1;" : "=f"(y) : "f"(x)); return y;
}
__device__ __forceinline__ float sig_a(float x){
    return fmaf(tanh_a(0.5f*x), 0.5f, 0.5f);
}

// packed fp32x2 helpers (Blackwell FFMA2)
__device__ __forceinline__ ull pack2(float x){
    ull r; unsigned u = __float_as_uint(x);
    asm("mov.b64 %0, {%1,%1};" : "=l"(r) : "r"(u));
    return r;
}
__device__ __forceinline__ ull packab(float a, float b){
    ull r;
    asm("mov.b64 %0, {%1,%2};" : "=l"(r) : "r"(__float_as_uint(a)), "r"(__float_as_uint(b)));
    return r;
}
__device__ __forceinline__ void fma2(ull &a, ull h, ull u){
    asm("fma.rn.f32x2 %0, %1, %2, %0;" : "+l"(a) : "l"(h), "l"(u));
}
__device__ __forceinline__ float2 unpack2(ull v){
    unsigned lo, hi;
    asm("mov.b64 {%0,%1}, %2;" : "=r"(lo), "=r"(hi) : "l"(v));
    return make_float2(__uint_as_float(lo), __uint_as_float(hi));
}

// mbarrier helpers
__device__ __forceinline__ uint32_t smem_u32(const void* p){
    uint32_t a;
    asm("{ .reg .u64 ta; cvta.to.shared.u64 ta, %1; cvt.u32.u64 %0, ta; }"
        : "=r"(a) : "l"(p));
    return a;
}
__device__ __forceinline__ void mbar_init(uint32_t mb, uint32_t cnt){
    asm volatile("mbarrier.init.shared.b64 [%0], %1;" :: "r"(mb), "r"(cnt) : "memory");
}
__device__ __forceinline__ void mbar_expect_tx(uint32_t mb, uint32_t bytes){
    asm volatile("mbarrier.arrive.expect_tx.shared.b64 _, [%0], %1;"
                 :: "r"(mb), "r"(bytes) : "memory");
}
__device__ __forceinline__ void mbar_wait(uint32_t mb, uint32_t parity){
    uint32_t done;
    asm volatile(
        "{\n\t.reg .pred p;\n\t"
        "mbarrier.try_wait.parity.acquire.cta.shared::cta.b64 p, [%1], %2;\n\t"
        "selp.b32 %0, 1, 0, p;\n\t}"
        : "=r"(done) : "r"(mb), "r"(parity) : "memory");
    if (!done) {
        asm volatile(
            "{\n\t.reg .pred P1;\n\t"
            "WAIT_LOOP_%=:\n\t"
            "mbarrier.try_wait.parity.acquire.cta.shared::cta.b64 P1, [%0], %1, 0x989680;\n\t"
            "@P1 bra.uni WAIT_DONE_%=;\n\t"
            "bra.uni WAIT_LOOP_%=;\n\t"
            "WAIT_DONE_%=:\n\t}"
            :: "r"(mb), "r"(parity) : "memory");
    }
}

// ---------------- lens ------------------------------------------------------
__global__ void lens_kernel(const int* __restrict__ text, float* __restrict__ out_lens)
{
    int b = blockIdx.x;
    int cnt = 0;
    for (int s = threadIdx.x; s < SEQ; s += blockDim.x)
        cnt += (text[b*SEQ + s] != 0);
    for (int o = 16; o; o >>= 1) cnt += __shfl_down_sync(0xffffffffu, cnt, o);
    __shared__ int ws[4];
    if ((threadIdx.x & 31) == 0) ws[threadIdx.x >> 5] = cnt;
    __syncthreads();
    if (threadIdx.x == 0) {
        int t = ws[0] + ws[1] + ws[2] + ws[3];
        g_lens[b] = t;
        out_lens[b] = (float)t;
    }
}

// ---------------- fused embedding gather + input projection ----------------
#define AS_STRIDE 68   // 64 rows + pad
__global__ void __launch_bounds__(256)
inproj_kernel(const int* __restrict__ text, const float* __restrict__ emb,
              const float* __restrict__ W_f, const float* __restrict__ W_b,
              const float* __restrict__ b_f, const float* __restrict__ b_b)
{
    extern __shared__ float sm[];
    float* As = sm;                     // [128 k][AS_STRIDE]
    float* Bs = sm + 128*AS_STRIDE;     // [128 k][128 cols]

    const int nb = blockIdx.x, mb = blockIdx.y, d = blockIdx.z;
    const int tid = threadIdx.x;
    const int row0 = mb*64;
    const int col0 = nb*128;
    const float* W    = d ? W_b : W_f;
    const float* bias = d ? b_b : b_f;

    for (int i = tid; i < 64*128; i += 256) {
        int r = i >> 7, k = i & 127;
        int tok = text[row0 + r];
        As[k*AS_STRIDE + r] = emb[(size_t)tok*EMBD + k];
    }
    for (int i = tid; i < 128*128; i += 256) {
        int k = i >> 7, cc = i & 127;
        Bs[i] = W[(size_t)k*G4 + col0 + cc];
    }
    __syncthreads();

    const int ty = tid >> 5, tx = tid & 31;
    ull acc[8][2];
    #pragma unroll
    for (int j = 0; j < 8; j++) acc[j][0] = acc[j][1] = 0ULL;

    const ulonglong2* Bs2 = (const ulonglong2*)Bs;
    #pragma unroll 4
    for (int k = 0; k < 128; k++) {
        ulonglong2 bp = Bs2[k*32 + tx];
        float4 a0 = *(const float4*)(As + k*AS_STRIDE + ty*8);
        float4 a1 = *(const float4*)(As + k*AS_STRIDE + ty*8 + 4);
        ull ad;
        ad = pack2(a0.x); fma2(acc[0][0], ad, bp.x); fma2(acc[0][1], ad, bp.y);
        ad = pack2(a0.y); fma2(acc[1][0], ad, bp.x); fma2(acc[1][1], ad, bp.y);
        ad = pack2(a0.z); fma2(acc[2][0], ad, bp.x); fma2(acc[2][1], ad, bp.y);
        ad = pack2(a0.w); fma2(acc[3][0], ad, bp.x); fma2(acc[3][1], ad, bp.y);
        ad = pack2(a1.x); fma2(acc[4][0], ad, bp.x); fma2(acc[4][1], ad, bp.y);
        ad = pack2(a1.y); fma2(acc[5][0], ad, bp.x); fma2(acc[5][1], ad, bp.y);
        ad = pack2(a1.z); fma2(acc[6][0], ad, bp.x); fma2(acc[6][1], ad, bp.y);
        ad = pack2(a1.w); fma2(acc[7][0], ad, bp.x); fma2(acc[7][1], ad, bp.y);
    }
    float4 bb = *(const float4*)(bias + col0 + tx*4);
    float* outp = g_xz + (size_t)d*NROWS*G4;
    #pragma unroll
    for (int j = 0; j < 8; j++) {
        float2 lo = unpack2(acc[j][0]);
        float2 hi = unpack2(acc[j][1]);
        float4 v = make_float4(lo.x+bb.x, lo.y+bb.y, hi.x+bb.z, hi.y+bb.w);
        *(float4*)(outp + (size_t)(row0 + ty*8 + j)*G4 + col0 + tx*4) = v;
    }
}

// ---------------- LSTM scan: persistent-U, st.async dataflow sync ----------
// grid (8,8,2): x = hidden-group (cluster dim), y = batch-group, z = dir.
// Sync: per-buffer full-mbarriers with tx counting. Each step, the 128 even-b
// threads st.async their packed h-pair to all 8 cluster CTAs; the receive
// mbarrier completes at exactly 8KB. No cluster barrier, no explicit drain;
// CTAs may skew +-1 step. zs partials double-buffered -> 1 __syncthreads/step.
#define ZS_STRIDE 132
__global__ void __cluster_dims__(8,1,1) __launch_bounds__(256,1)
lstm_kernel(const float* __restrict__ Uf, const float* __restrict__ Ub)
{
    extern __shared__ float sm[];
    float* Us  = sm;                          // [256 k][128 lc]       131072 B
    ull*   hb2 = (ull*)(sm + 256*128);        // [2][256 k][4 bpair]    16384 B
    ull*   zs2 = hb2 + 2*256*4;               // [2][16 row][ZS_STRIDE] 33792 B
    ull*   mbs = zs2 + 2*16*ZS_STRIDE;        // full[0], full[1]          16 B

    const int c   = blockIdx.x;
    const int g   = blockIdx.y;
    const int d   = blockIdx.z;
    const int tid = threadIdx.x;
    const float* U = d ? Ub : Uf;

    const uint32_t hb2_u32 = smem_u32(hb2);
    const uint32_t mb_u32  = smem_u32(mbs);

    // U slice: local col lc = q*32+jj -> global col q*256 + c*32 + jj
    for (int i = tid; i < 256*128; i += 256) {
        int k = i >> 7, lc = i & 127;
        int q = lc >> 5, jj = lc & 31;
        Us[i] = U[(size_t)k*G4 + q*HID + c*32 + jj];
    }
    for (int i = tid; i < 256*4; i += 256) hb2[i] = 0ULL;   // h0 = 0 (buffer 0)
    if (tid == 0) {
        mbar_init(mb_u32,     1);
        mbar_init(mb_u32 + 8, 1);
        mbar_expect_tx(mb_u32,     8192);   // full[0] phase 0
        mbar_expect_tx(mb_u32 + 8, 8192);   // full[1] phase 0
    }
    __syncthreads();
    // mbarriers must be cluster-visible before any peer st.async
    asm volatile("barrier.cluster.arrive.aligned;" ::: "memory");
    asm volatile("barrier.cluster.wait.aligned;"   ::: "memory");

    // FMA-phase mapping
    const int w    = tid >> 5, lane = tid & 31;
    const int kq   = w >> 1;
    const int cg   = w & 1;
    const int lc0  = cg*64 + lane*2;

    // gate-phase mapping
    const int b   = tid & 7;
    const int hid = tid >> 3;
    const int bg  = g*8 + b;
    const float* xzb = g_xz + (size_t)d*NROWS*G4 + (size_t)bg*SEQ*G4 + c*32 + hid;
    float cstate = 0.f;

    int ph0 = 0, ph1 = 0;   // per-buffer phase counters (identical on all threads)

    for (int s = 0; s < SEQ; s++) {
        const int t = d ? (SEQ - 1 - s) : s;
        const int p = s & 1;

        // prefetch xz gate inputs (consumed after FMA + sync)
        const float* xzr = xzb + (size_t)t*G4;
        float xz0 = __ldg(xzr);
        float xz1 = __ldg(xzr + 256);
        float xz2 = __ldg(xzr + 512);
        float xz3 = __ldg(xzr + 768);

        // wait for this step's h (step 0 reads locally-zeroed buffer 0)
        if (s > 0) {
            uint32_t mb = mb_u32 + p*8;
            int phase = p ? (ph1 & 1) : (ph0 & 1);
            mbar_wait(mb, (uint32_t)phase);
            if (tid == 0) mbar_expect_tx(mb, 8192);
            if (p) ph1++; else ph0++;
        }

        // ---- h @ U partial (this warp's k quarter, col pair) ----
        ull acc[4][2];
        #pragma unroll
        for (int pp = 0; pp < 4; pp++) acc[pp][0] = acc[pp][1] = 0ULL;

        const ull* hrow = hb2 + (size_t)p*1024 + (size_t)kq*64*4;
        const float* Uk = Us + kq*64*128 + lc0;
        #pragma unroll 4
        for (int kk = 0; kk < 64; kk++) {
            float2 u = *(const float2*)(Uk + kk*128);
            ull u0 = pack2(u.x), u1 = pack2(u.y);
            ulonglong2 hA = *(const ulonglong2*)(hrow + kk*4);
            ulonglong2 hB = *(const ulonglong2*)(hrow + kk*4 + 2);
            fma2(acc[0][0], hA.x, u0); fma2(acc[0][1], hA.x, u1);
            fma2(acc[1][0], hA.y, u0); fma2(acc[1][1], hA.y, u1);
            fma2(acc[2][0], hB.x, u0); fma2(acc[2][1], hB.x, u1);
            fma2(acc[3][0], hB.y, u0); fma2(acc[3][1], hB.y, u1);
        }
        ull* zrow = zs2 + (size_t)p*16*ZS_STRIDE;
        #pragma unroll
        for (int pp = 0; pp < 4; pp++) {
            *(ulonglong2*)(zrow + (size_t)(kq*4 + pp)*ZS_STRIDE + lc0) =
                make_ulonglong2(acc[pp][0], acc[pp][1]);
        }
        __syncthreads();

        // ---- gates ----
        float zsum[4];
        #pragma unroll
        for (int q = 0; q < 4; q++) {
            float ssum = (q==0) ? xz0 : (q==1) ? xz1 : (q==2) ? xz2 : xz3;
            #pragma unroll
            for (int k2 = 0; k2 < 4; k2++) {
                const float* zp = (const float*)(zrow + (size_t)(k2*4 + (b>>1))*ZS_STRIDE
                                                 + q*32 + hid) + (b & 1);
                ssum += *zp;
            }
            zsum[q] = ssum;
        }
        cstate = sig_a(zsum[1])*cstate + sig_a(zsum[0])*tanh_a(zsum[2]);
        float hv = sig_a(zsum[3])*tanh_a(cstate);

        g_h[((size_t)bg*SEQ + t)*(2*HID) + d*HID + c*32 + hid] = hv;

        // send packed (even b, odd b) pair to all 8 cluster CTAs (skip last step)
        float hpart = __shfl_xor_sync(0xffffffffu, hv, 1);
        if (s < SEQ-1 && !(b & 1)) {
            ull pairv = packab(hv, hpart);
            uint32_t laddr = hb2_u32 +
                (uint32_t)((((1 - p)*256 + c*32 + hid)*4 + (b >> 1)) * 8);
            uint32_t lmb = mb_u32 + (1 - p)*8;
            #pragma unroll
            for (int r = 0; r < 8; r++) {
                uint32_t raddr, rmb;
                asm volatile("mapa.shared::cluster.u32 %0, %1, %2;"
                             : "=r"(raddr) : "r"(laddr), "r"(r));
                asm volatile("mapa.shared::cluster.u32 %0, %1, %2;"
                             : "=r"(rmb) : "r"(lmb), "r"(r));
                asm volatile("st.async.shared::cluster.mbarrier::complete_tx::bytes.b64 "
                             "[%0], %1, [%2];"
                             :: "r"(raddr), "l"(pairv), "r"(rmb) : "memory");
            }
        }
    }
}

// ---------------- logits = h @ W_d + b_d  (warp per row) -------------------
__global__ void __launch_bounds__(256)
logits_kernel(const float* __restrict__ Wd, const float* __restrict__ bd,
              float* __restrict__ out)
{
    __shared__ float Ws[2*HID*TAGS];
    const int tid = threadIdx.x;
    for (int i = tid; i < 2*HID*TAGS; i += 256) Ws[i] = Wd[i];
    __syncthreads();

    const int warp = tid >> 5, lane = tid & 31;
    const int row = blockIdx.x*8 + warp;
    const float* hr = g_h + (size_t)row*(2*HID);

    float a[TAGS];
    #pragma unroll
    for (int tg = 0; tg < TAGS; tg++) a[tg] = 0.f;
    for (int k = lane; k < 2*HID; k += 32) {
        float hv = hr[k];
        #pragma unroll
        for (int tg = 0; tg < TAGS; tg++) a[tg] = fmaf(hv, Ws[k*TAGS + tg], a[tg]);
    }
    #pragma unroll
    for (int tg = 0; tg < TAGS; tg++)
        for (int o = 16; o; o >>= 1) a[tg] += __shfl_down_sync(0xffffffffu, a[tg], o);
    if (lane == 0) {
        #pragma unroll
        for (int tg = 0; tg < TAGS; tg++)
            out[(size_t)row*TAGS + tg] = a[tg] + bd[tg];
    }
}

// ---------------- CRF -------------------------------------------------------
__global__ void crf_kernel(const int* __restrict__ labels, const float* __restrict__ trans,
                           const float* __restrict__ logits, float* __restrict__ out_ll)
{
    __shared__ float tr[TAGS*TAGS];
    __shared__ float alpha[TAGS];
    const int b = blockIdx.x;
    const int tid = threadIdx.x;

    for (int i = tid; i < TAGS*TAGS; i += 32) tr[i] = trans[i];
    const int len = g_lens[b];
    const float* lg = logits + (size_t)b*SEQ*TAGS;
    if (tid < TAGS) alpha[tid] = lg[tid];
    __syncwarp();

    for (int t = 1; t < len; t++) {
        float nv = 0.f;
        if (tid < TAGS) {
            float m = -1e30f;
            #pragma unroll
            for (int i = 0; i < TAGS; i++) m = fmaxf(m, alpha[i] + tr[i*TAGS + tid]);
            float s = 0.f;
            #pragma unroll
            for (int i = 0; i < TAGS; i++) s += __expf(alpha[i] + tr[i*TAGS + tid] - m);
            nv = m + __logf(s) + lg[t*TAGS + tid];
        }
        __syncwarp();
        if (tid < TAGS) alpha[tid] = nv;
        __syncwarp();
    }

    const int* lb = labels + b*SEQ;
    float sc = 0.f;
    for (int t = tid; t < len; t += 32)      sc += lg[t*TAGS + lb[t]];
    for (int t = tid; t + 1 < len; t += 32)  sc += tr[lb[t]*TAGS + lb[t+1]];
    for (int o = 16; o; o >>= 1) sc += __shfl_down_sync(0xffffffffu, sc, o);

    if (tid == 0) {
        float m = -1e30f;
        #pragma unroll
        for (int i = 0; i < TAGS; i++) m = fmaxf(m, alpha[i]);
        float s = 0.f;
        #pragma unroll
        for (int i = 0; i < TAGS; i++) s += __expf(alpha[i] - m);
        out_ll[b] = sc - (m + __logf(s));
    }
}

// ---------------- launch ----------------------------------------------------
extern "C" void kernel_launch(void* const* d_in, const int* in_sizes, int n_in,
                              void* d_out, int out_size)
{
    (void)in_sizes; (void)n_in; (void)out_size;
    const int*   text   = (const int*)  d_in[0];
    const int*   labels = (const int*)  d_in[1];
    const float* emb    = (const float*)d_in[2];
    const float* W_f    = (const float*)d_in[3];
    const float* U_f    = (const float*)d_in[4];
    const float* b_f    = (const float*)d_in[5];
    const float* W_b    = (const float*)d_in[6];
    const float* U_b    = (const float*)d_in[7];
    const float* b_b    = (const float*)d_in[8];
    const float* W_d    = (const float*)d_in[9];
    const float* b_d    = (const float*)d_in[10];
    const float* trans  = (const float*)d_in[11];
    float* out = (float*)d_out;

    const int gemm_smem = (128*AS_STRIDE + 128*128) * 4;                  // 100352
    const int lstm_smem = 256*128*4 + 2*256*4*8 + 2*16*ZS_STRIDE*8 + 64;  // 181312
    cudaFuncSetAttribute(inproj_kernel, cudaFuncAttributeMaxDynamicSharedMemorySize, gemm_smem);
    cudaFuncSetAttribute(lstm_kernel,   cudaFuncAttributeMaxDynamicSharedMemorySize, lstm_smem);

    lens_kernel<<<BATCH, 128>>>(text, out + LOGITS_N);

    dim3 ggrid(8, NROWS/64, 2);
    inproj_kernel<<<ggrid, 256, gemm_smem>>>(text, emb, W_f, W_b, b_f, b_b);

    // pad launch (idempotent) so the ncu capture slot lands on lstm_kernel
    lens_kernel<<<BATCH, 128>>>(text, out + LOGITS_N);

    dim3 lgrid(8, 8, 2);
    lstm_kernel<<<lgrid, 256, lstm_smem>>>(U_f, U_b);

    logits_kernel<<<NROWS/8, 256>>>(W_d, b_d, out);

    crf_kernel<<<BATCH, 32>>>(labels, trans, out, out + LOGITS_N + BATCH);
}

// round 11
// speedup vs baseline: 2.4069x; 1.0195x over previous
#include <cuda_runtime.h>
#include <cstdint>
#include <math.h>

#define BATCH 64
#define SEQ   512
#define EMBD  128
#define HID   256
#define TAGS  9
#define G4    1024            // 4*HID
#define NROWS (BATCH*SEQ)     // 32768
#define LOGITS_N (NROWS*TAGS) // 294912

typedef unsigned long long ull;

// ---------------- scratch ---------------------------------------------------
__device__ float g_xz[2ull*NROWS*G4];          // 256MB: pre-activations per dir
__device__ float g_h[(size_t)NROWS*2*HID];     // 64MB:  concat [fwd|bwd] hidden
__device__ int   g_lens[BATCH];

// fast HW tanh (MUFU.TANH) + sigmoid via tanh
__device__ __forceinline__ float tanh_a(float x){
    float y; asm("tanh.approx.f32 %0, %1;" : "=f"(y) : "f"(x)); return y;
}
__device__ __forceinline__ float sig_a(float x){
    return fmaf(tanh_a(0.5f*x), 0.5f, 0.5f);
}

// packed fp32x2 helpers (Blackwell FFMA2)
__device__ __forceinline__ ull pack2(float x){
    ull r; unsigned u = __float_as_uint(x);
    asm("mov.b64 %0, {%1,%1};" : "=l"(r) : "r"(u));
    return r;
}
__device__ __forceinline__ ull packab(float a, float b){
    ull r;
    asm("mov.b64 %0, {%1,%2};" : "=l"(r) : "r"(__float_as_uint(a)), "r"(__float_as_uint(b)));
    return r;
}
__device__ __forceinline__ void fma2(ull &a, ull h, ull u){
    asm("fma.rn.f32x2 %0, %1, %2, %0;" : "+l"(a) : "l"(h), "l"(u));
}
__device__ __forceinline__ float2 unpack2(ull v){
    unsigned lo, hi;
    asm("mov.b64 {%0,%1}, %2;" : "=r"(lo), "=r"(hi) : "l"(v));
    return make_float2(__uint_as_float(lo), __uint_as_float(hi));
}

// mbarrier helpers
__device__ __forceinline__ uint32_t smem_u32(const void* p){
    uint32_t a;
    asm("{ .reg .u64 ta; cvta.to.shared.u64 ta, %1; cvt.u32.u64 %0, ta; }"
        : "=r"(a) : "l"(p));
    return a;
}
__device__ __forceinline__ void mbar_init(uint32_t mb, uint32_t cnt){
    asm volatile("mbarrier.init.shared.b64 [%0], %1;" :: "r"(mb), "r"(cnt) : "memory");
}
__device__ __forceinline__ void mbar_expect_tx(uint32_t mb, uint32_t bytes){
    asm volatile("mbarrier.arrive.expect_tx.shared.b64 _, [%0], %1;"
                 :: "r"(mb), "r"(bytes) : "memory");
}
__device__ __forceinline__ void mbar_wait(uint32_t mb, uint32_t parity){
    uint32_t done;
    asm volatile(
        "{\n\t.reg .pred p;\n\t"
        "mbarrier.try_wait.parity.acquire.cta.shared::cta.b64 p, [%1], %2;\n\t"
        "selp.b32 %0, 1, 0, p;\n\t}"
        : "=r"(done) : "r"(mb), "r"(parity) : "memory");
    if (!done) {
        asm volatile(
            "{\n\t.reg .pred P1;\n\t"
            "WAIT_LOOP_%=:\n\t"
            "mbarrier.try_wait.parity.acquire.cta.shared::cta.b64 P1, [%0], %1, 0x989680;\n\t"
            "@P1 bra.uni WAIT_DONE_%=;\n\t"
            "bra.uni WAIT_LOOP_%=;\n\t"
            "WAIT_DONE_%=:\n\t}"
            :: "r"(mb), "r"(parity) : "memory");
    }
}

// ---------------- lens ------------------------------------------------------
__global__ void lens_kernel(const int* __restrict__ text, float* __restrict__ out_lens)
{
    int b = blockIdx.x;
    int cnt = 0;
    for (int s = threadIdx.x; s < SEQ; s += blockDim.x)
        cnt += (text[b*SEQ + s] != 0);
    for (int o = 16; o; o >>= 1) cnt += __shfl_down_sync(0xffffffffu, cnt, o);
    __shared__ int ws[4];
    if ((threadIdx.x & 31) == 0) ws[threadIdx.x >> 5] = cnt;
    __syncthreads();
    if (threadIdx.x == 0) {
        int t = ws[0] + ws[1] + ws[2] + ws[3];
        g_lens[b] = t;
        out_lens[b] = (float)t;
    }
}

// ---------------- fused embedding gather + input projection ----------------
#define AS_STRIDE 68   // 64 rows + pad
__global__ void __launch_bounds__(256)
inproj_kernel(const int* __restrict__ text, const float* __restrict__ emb,
              const float* __restrict__ W_f, const float* __restrict__ W_b,
              const float* __restrict__ b_f, const float* __restrict__ b_b)
{
    extern __shared__ float sm[];
    float* As = sm;                     // [128 k][AS_STRIDE]
    float* Bs = sm + 128*AS_STRIDE;     // [128 k][128 cols]

    const int nb = blockIdx.x, mb = blockIdx.y, d = blockIdx.z;
    const int tid = threadIdx.x;
    const int row0 = mb*64;
    const int col0 = nb*128;
    const float* W    = d ? W_b : W_f;
    const float* bias = d ? b_b : b_f;

    for (int i = tid; i < 64*128; i += 256) {
        int r = i >> 7, k = i & 127;
        int tok = text[row0 + r];
        As[k*AS_STRIDE + r] = emb[(size_t)tok*EMBD + k];
    }
    for (int i = tid; i < 128*128; i += 256) {
        int k = i >> 7, cc = i & 127;
        Bs[i] = W[(size_t)k*G4 + col0 + cc];
    }
    __syncthreads();

    const int ty = tid >> 5, tx = tid & 31;
    ull acc[8][2];
    #pragma unroll
    for (int j = 0; j < 8; j++) acc[j][0] = acc[j][1] = 0ULL;

    const ulonglong2* Bs2 = (const ulonglong2*)Bs;
    #pragma unroll 4
    for (int k = 0; k < 128; k++) {
        ulonglong2 bp = Bs2[k*32 + tx];
        float4 a0 = *(const float4*)(As + k*AS_STRIDE + ty*8);
        float4 a1 = *(const float4*)(As + k*AS_STRIDE + ty*8 + 4);
        ull ad;
        ad = pack2(a0.x); fma2(acc[0][0], ad, bp.x); fma2(acc[0][1], ad, bp.y);
        ad = pack2(a0.y); fma2(acc[1][0], ad, bp.x); fma2(acc[1][1], ad, bp.y);
        ad = pack2(a0.z); fma2(acc[2][0], ad, bp.x); fma2(acc[2][1], ad, bp.y);
        ad = pack2(a0.w); fma2(acc[3][0], ad, bp.x); fma2(acc[3][1], ad, bp.y);
        ad = pack2(a1.x); fma2(acc[4][0], ad, bp.x); fma2(acc[4][1], ad, bp.y);
        ad = pack2(a1.y); fma2(acc[5][0], ad, bp.x); fma2(acc[5][1], ad, bp.y);
        ad = pack2(a1.z); fma2(acc[6][0], ad, bp.x); fma2(acc[6][1], ad, bp.y);
        ad = pack2(a1.w); fma2(acc[7][0], ad, bp.x); fma2(acc[7][1], ad, bp.y);
    }
    float4 bb = *(const float4*)(bias + col0 + tx*4);
    float* outp = g_xz + (size_t)d*NROWS*G4;
    #pragma unroll
    for (int j = 0; j < 8; j++) {
        float2 lo = unpack2(acc[j][0]);
        float2 hi = unpack2(acc[j][1]);
        float4 v = make_float4(lo.x+bb.x, lo.y+bb.y, hi.x+bb.z, hi.y+bb.w);
        *(float4*)(outp + (size_t)(row0 + ty*8 + j)*G4 + col0 + tx*4) = v;
    }
}

// ---------------- LSTM scan: persistent-U, st.async, 512 threads -----------
// grid (8,8,2): x = hidden-group (cluster dim), y = batch-group, z = dir.
// 16 warps: warp = (kq 0..7 : 32-k slice, ch 0..1 : 64-col half).
// Lane owns a col pair; 8 batches packed as 4 f32x2 batch-pair accumulators.
// U read once per step; 8 k-split partials in double-buffered zs; gate phase
// on threads 0..255 sums 8 partials + xz, applies gates, st.asyncs the packed
// h-pair to all 8 cluster CTAs (tx-counting mbarrier = the step barrier).
// Send fan-out split: even-b threads -> ranks 0..3, odd-b -> ranks 4..7
// (both construct the identical (even,odd) packed pair after shfl.xor).
#define ZS_STRIDE 132
#define NTHR 512
__global__ void __cluster_dims__(8,1,1) __launch_bounds__(NTHR,1)
lstm_kernel(const float* __restrict__ Uf, const float* __restrict__ Ub)
{
    extern __shared__ float sm[];
    float* Us  = sm;                          // [256 k][128 lc]       131072 B
    ull*   hb2 = (ull*)(sm + 256*128);        // [2][256 k][4 bpair]    16384 B
    ull*   zs2 = hb2 + 2*256*4;               // [2][32 row][ZS_STRIDE] 67584 B
    ull*   mbs = zs2 + 2*32*ZS_STRIDE;        // full[0], full[1]          16 B

    const int c   = blockIdx.x;
    const int g   = blockIdx.y;
    const int d   = blockIdx.z;
    const int tid = threadIdx.x;
    const float* U = d ? Ub : Uf;

    const uint32_t hb2_u32 = smem_u32(hb2);
    const uint32_t mb_u32  = smem_u32(mbs);

    // U slice: local col lc = q*32+jj -> global col q*256 + c*32 + jj
    for (int i = tid; i < 256*128; i += NTHR) {
        int k = i >> 7, lc = i & 127;
        int q = lc >> 5, jj = lc & 31;
        Us[i] = U[(size_t)k*G4 + q*HID + c*32 + jj];
    }
    for (int i = tid; i < 256*4; i += NTHR) hb2[i] = 0ULL;   // h0 = 0 (buffer 0)
    if (tid == 0) {
        mbar_init(mb_u32,     1);
        mbar_init(mb_u32 + 8, 1);
        mbar_expect_tx(mb_u32,     8192);   // full[0] phase 0
        mbar_expect_tx(mb_u32 + 8, 8192);   // full[1] phase 0
    }
    __syncthreads();
    // mbarriers must be cluster-visible before any peer st.async
    asm volatile("barrier.cluster.arrive.aligned;" ::: "memory");
    asm volatile("barrier.cluster.wait.aligned;"   ::: "memory");

    // FMA-phase mapping: 16 warps
    const int w    = tid >> 5, lane = tid & 31;
    const int kq   = w >> 1;            // 32-k slice [kq*32, kq*32+32)
    const int cg   = w & 1;             // col half
    const int lc0  = cg*64 + lane*2;    // local col pair

    // gate-phase mapping (threads 0..255)
    const int b   = tid & 7;
    const int hid = (tid >> 3) & 31;
    const int bg  = g*8 + b;
    const bool gate_thr = (tid < 256);
    const float* xzb = g_xz + (size_t)d*NROWS*G4 + (size_t)bg*SEQ*G4 + c*32 + hid;
    float cstate = 0.f;

    int ph0 = 0, ph1 = 0;

    for (int s = 0; s < SEQ; s++) {
        const int t = d ? (SEQ - 1 - s) : s;
        const int p = s & 1;

        // prefetch xz gate inputs (in flight across the wait + FMA phase)
        float xz0 = 0.f, xz1 = 0.f, xz2 = 0.f, xz3 = 0.f;
        if (gate_thr) {
            const float* xzr = xzb + (size_t)t*G4;
            xz0 = __ldg(xzr);
            xz1 = __ldg(xzr + 256);
            xz2 = __ldg(xzr + 512);
            xz3 = __ldg(xzr + 768);
        }

        // wait for this step's h (step 0 reads locally-zeroed buffer 0)
        if (s > 0) {
            uint32_t mb = mb_u32 + p*8;
            int phase = p ? (ph1 & 1) : (ph0 & 1);
            mbar_wait(mb, (uint32_t)phase);
            if (tid == 0) mbar_expect_tx(mb, 8192);
            if (p) ph1++; else ph0++;
        }

        // ---- h @ U partial (this warp's 32-k slice, col pair) ----
        ull acc[4][2];
        #pragma unroll
        for (int pp = 0; pp < 4; pp++) acc[pp][0] = acc[pp][1] = 0ULL;

        const ull* hrow = hb2 + (size_t)p*1024 + (size_t)kq*32*4;
        const float* Uk = Us + kq*32*128 + lc0;
        #pragma unroll 4
        for (int kk = 0; kk < 32; kk++) {
            float2 u = *(const float2*)(Uk + kk*128);
            ull u0 = pack2(u.x), u1 = pack2(u.y);
            ulonglong2 hA = *(const ulonglong2*)(hrow + kk*4);
            ulonglong2 hB = *(const ulonglong2*)(hrow + kk*4 + 2);
            fma2(acc[0][0], hA.x, u0); fma2(acc[0][1], hA.x, u1);
            fma2(acc[1][0], hA.y, u0); fma2(acc[1][1], hA.y, u1);
            fma2(acc[2][0], hB.x, u0); fma2(acc[2][1], hB.x, u1);
            fma2(acc[3][0], hB.y, u0); fma2(acc[3][1], hB.y, u1);
        }
        ull* zrow = zs2 + (size_t)p*32*ZS_STRIDE;
        #pragma unroll
        for (int pp = 0; pp < 4; pp++) {
            *(ulonglong2*)(zrow + (size_t)(kq*4 + pp)*ZS_STRIDE + lc0) =
                make_ulonglong2(acc[pp][0], acc[pp][1]);
        }
        __syncthreads();

        // ---- gates (threads 0..255) ----
        if (gate_thr) {
            float zsum[4];
            #pragma unroll
            for (int q = 0; q < 4; q++) {
                float ssum = (q==0) ? xz0 : (q==1) ? xz1 : (q==2) ? xz2 : xz3;
                #pragma unroll
                for (int k2 = 0; k2 < 8; k2++) {
                    const float* zp = (const float*)(zrow + (size_t)(k2*4 + (b>>1))*ZS_STRIDE
                                                     + q*32 + hid) + (b & 1);
                    ssum += *zp;
                }
                zsum[q] = ssum;
            }
            cstate = sig_a(zsum[1])*cstate + sig_a(zsum[0])*tanh_a(zsum[2]);
            float hv = sig_a(zsum[3])*tanh_a(cstate);

            g_h[((size_t)bg*SEQ + t)*(2*HID) + d*HID + c*32 + hid] = hv;

            // both pair threads build the identical (even,odd) packed value;
            // even-b sends ranks 0..3, odd-b sends ranks 4..7
            float hpart = __shfl_xor_sync(0xffffffffu, hv, 1);
            if (s < SEQ-1) {
                ull pairv = (b & 1) ? packab(hpart, hv) : packab(hv, hpart);
                uint32_t laddr = hb2_u32 +
                    (uint32_t)((((1 - p)*256 + c*32 + hid)*4 + (b >> 1)) * 8);
                uint32_t lmb = mb_u32 + (1 - p)*8;
                const int r0 = (b & 1) * 4;
                #pragma unroll
                for (int rr = 0; rr < 4; rr++) {
                    uint32_t raddr, rmb;
                    asm volatile("mapa.shared::cluster.u32 %0, %1, %2;"
                                 : "=r"(raddr) : "r"(laddr), "r"(r0 + rr));
                    asm volatile("mapa.shared::cluster.u32 %0, %1, %2;"
                                 : "=r"(rmb) : "r"(lmb), "r"(r0 + rr));
                    asm volatile("st.async.shared::cluster.mbarrier::complete_tx::bytes.b64 "
                                 "[%0], %1, [%2];"
                                 :: "r"(raddr), "l"(pairv), "r"(rmb) : "memory");
                }
            }
        }
    }
}

// ---------------- logits = h @ W_d + b_d  (warp per row) -------------------
__global__ void __launch_bounds__(256)
logits_kernel(const float* __restrict__ Wd, const float* __restrict__ bd,
              float* __restrict__ out)
{
    __shared__ float Ws[2*HID*TAGS];
    const int tid = threadIdx.x;
    for (int i = tid; i < 2*HID*TAGS; i += 256) Ws[i] = Wd[i];
    __syncthreads();

    const int warp = tid >> 5, lane = tid & 31;
    const int row = blockIdx.x*8 + warp;
    const float* hr = g_h + (size_t)row*(2*HID);

    float a[TAGS];
    #pragma unroll
    for (int tg = 0; tg < TAGS; tg++) a[tg] = 0.f;
    for (int k = lane; k < 2*HID; k += 32) {
        float hv = hr[k];
        #pragma unroll
        for (int tg = 0; tg < TAGS; tg++) a[tg] = fmaf(hv, Ws[k*TAGS + tg], a[tg]);
    }
    #pragma unroll
    for (int tg = 0; tg < TAGS; tg++)
        for (int o = 16; o; o >>= 1) a[tg] += __shfl_down_sync(0xffffffffu, a[tg], o);
    if (lane == 0) {
        #pragma unroll
        for (int tg = 0; tg < TAGS; tg++)
            out[(size_t)row*TAGS + tg] = a[tg] + bd[tg];
    }
}

// ---------------- CRF -------------------------------------------------------
__global__ void crf_kernel(const int* __restrict__ labels, const float* __restrict__ trans,
                           const float* __restrict__ logits, float* __restrict__ out_ll)
{
    __shared__ float tr[TAGS*TAGS];
    __shared__ float alpha[TAGS];
    const int b = blockIdx.x;
    const int tid = threadIdx.x;

    for (int i = tid; i < TAGS*TAGS; i += 32) tr[i] = trans[i];
    const int len = g_lens[b];
    const float* lg = logits + (size_t)b*SEQ*TAGS;
    if (tid < TAGS) alpha[tid] = lg[tid];
    __syncwarp();

    for (int t = 1; t < len; t++) {
        float nv = 0.f;
        if (tid < TAGS) {
            float m = -1e30f;
            #pragma unroll
            for (int i = 0; i < TAGS; i++) m = fmaxf(m, alpha[i] + tr[i*TAGS + tid]);
            float s = 0.f;
            #pragma unroll
            for (int i = 0; i < TAGS; i++) s += __expf(alpha[i] + tr[i*TAGS + tid] - m);
            nv = m + __logf(s) + lg[t*TAGS + tid];
        }
        __syncwarp();
        if (tid < TAGS) alpha[tid] = nv;
        __syncwarp();
    }

    const int* lb = labels + b*SEQ;
    float sc = 0.f;
    for (int t = tid; t < len; t += 32)      sc += lg[t*TAGS + lb[t]];
    for (int t = tid; t + 1 < len; t += 32)  sc += tr[lb[t]*TAGS + lb[t+1]];
    for (int o = 16; o; o >>= 1) sc += __shfl_down_sync(0xffffffffu, sc, o);

    if (tid == 0) {
        float m = -1e30f;
        #pragma unroll
        for (int i = 0; i < TAGS; i++) m = fmaxf(m, alpha[i]);
        float s = 0.f;
        #pragma unroll
        for (int i = 0; i < TAGS; i++) s += __expf(alpha[i] - m);
        out_ll[b] = sc - (m + __logf(s));
    }
}

// ---------------- launch ----------------------------------------------------
extern "C" void kernel_launch(void* const* d_in, const int* in_sizes, int n_in,
                              void* d_out, int out_size)
{
    (void)in_sizes; (void)n_in; (void)out_size;
    const int*   text   = (const int*)  d_in[0];
    const int*   labels = (const int*)  d_in[1];
    const float* emb    = (const float*)d_in[2];
    const float* W_f    = (const float*)d_in[3];
    const float* U_f    = (const float*)d_in[4];
    const float* b_f    = (const float*)d_in[5];
    const float* W_b    = (const float*)d_in[6];
    const float* U_b    = (const float*)d_in[7];
    const float* b_b    = (const float*)d_in[8];
    const float* W_d    = (const float*)d_in[9];
    const float* b_d    = (const float*)d_in[10];
    const float* trans  = (const float*)d_in[11];
    float* out = (float*)d_out;

    const int gemm_smem = (128*AS_STRIDE + 128*128) * 4;                  // 100352
    const int lstm_smem = 256*128*4 + 2*256*4*8 + 2*32*ZS_STRIDE*8 + 64;  // 215104
    cudaFuncSetAttribute(inproj_kernel, cudaFuncAttributeMaxDynamicSharedMemorySize, gemm_smem);
    cudaFuncSetAttribute(lstm_kernel,   cudaFuncAttributeMaxDynamicSharedMemorySize, lstm_smem);

    lens_kernel<<<BATCH, 128>>>(text, out + LOGITS_N);

    dim3 ggrid(8, NROWS/64, 2);
    inproj_kernel<<<ggrid, 256, gemm_smem>>>(text, emb, W_f, W_b, b_f, b_b);

    // pad launch (idempotent) so the ncu capture slot lands on lstm_kernel
    lens_kernel<<<BATCH, 128>>>(text, out + LOGITS_N);

    dim3 lgrid(8, 8, 2);
    lstm_kernel<<<lgrid, NTHR, lstm_smem>>>(U_f, U_b);

    logits_kernel<<<NROWS/8, 256>>>(W_d, b_d, out);

    crf_kernel<<<BATCH, 32>>>(labels, trans, out, out + LOGITS_N + BATCH);
}

// round 12
// speedup vs baseline: 2.5168x; 1.0457x over previous
#include <cuda_runtime.h>
#include <cstdint>
#include <math.h>

#define BATCH 64
#define SEQ   512
#define EMBD  128
#define HID   256
#define TAGS  9
#define G4    1024            // 4*HID
#define NROWS (BATCH*SEQ)     // 32768
#define LOGITS_N (NROWS*TAGS) // 294912

typedef unsigned long long ull;

// ---------------- scratch ---------------------------------------------------
__device__ float g_xz[2ull*NROWS*G4];          // 256MB: pre-activations per dir
__device__ float g_h[(size_t)NROWS*2*HID];     // 64MB:  concat [fwd|bwd] hidden
__device__ int   g_lens[BATCH];

// fast HW tanh (MUFU.TANH) + sigmoid via tanh
__device__ __forceinline__ float tanh_a(float x){
    float y; asm("tanh.approx.f32 %0, %1;" : "=f"(y) : "f"(x)); return y;
}
__device__ __forceinline__ float sig_a(float x){
    return fmaf(tanh_a(0.5f*x), 0.5f, 0.5f);
}

// packed fp32x2 helpers (Blackwell FFMA2)
__device__ __forceinline__ ull pack2(float x){
    ull r; unsigned u = __float_as_uint(x);
    asm("mov.b64 %0, {%1,%1};" : "=l"(r) : "r"(u));
    return r;
}
__device__ __forceinline__ ull packab(float a, float b){
    ull r;
    asm("mov.b64 %0, {%1,%2};" : "=l"(r) : "r"(__float_as_uint(a)), "r"(__float_as_uint(b)));
    return r;
}
__device__ __forceinline__ void fma2(ull &a, ull h, ull u){
    asm("fma.rn.f32x2 %0, %1, %2, %0;" : "+l"(a) : "l"(h), "l"(u));
}
__device__ __forceinline__ float2 unpack2(ull v){
    unsigned lo, hi;
    asm("mov.b64 {%0,%1}, %2;" : "=r"(lo), "=r"(hi) : "l"(v));
    return make_float2(__uint_as_float(lo), __uint_as_float(hi));
}

// mbarrier helpers
__device__ __forceinline__ uint32_t smem_u32(const void* p){
    uint32_t a;
    asm("{ .reg .u64 ta; cvta.to.shared.u64 ta, %1; cvt.u32.u64 %0, ta; }"
        : "=r"(a) : "l"(p));
    return a;
}
__device__ __forceinline__ void mbar_init(uint32_t mb, uint32_t cnt){
    asm volatile("mbarrier.init.shared.b64 [%0], %1;" :: "r"(mb), "r"(cnt) : "memory");
}
__device__ __forceinline__ void mbar_expect_tx(uint32_t mb, uint32_t bytes){
    asm volatile("mbarrier.arrive.expect_tx.shared.b64 _, [%0], %1;"
                 :: "r"(mb), "r"(bytes) : "memory");
}
__device__ __forceinline__ void mbar_wait(uint32_t mb, uint32_t parity){
    uint32_t done;
    asm volatile(
        "{\n\t.reg .pred p;\n\t"
        "mbarrier.try_wait.parity.acquire.cta.shared::cta.b64 p, [%1], %2;\n\t"
        "selp.b32 %0, 1, 0, p;\n\t}"
        : "=r"(done) : "r"(mb), "r"(parity) : "memory");
    if (!done) {
        asm volatile(
            "{\n\t.reg .pred P1;\n\t"
            "WAIT_LOOP_%=:\n\t"
            "mbarrier.try_wait.parity.acquire.cta.shared::cta.b64 P1, [%0], %1, 0x989680;\n\t"
            "@P1 bra.uni WAIT_DONE_%=;\n\t"
            "bra.uni WAIT_LOOP_%=;\n\t"
            "WAIT_DONE_%=:\n\t}"
            :: "r"(mb), "r"(parity) : "memory");
    }
}

// ---------------- lens ------------------------------------------------------
__global__ void lens_kernel(const int* __restrict__ text, float* __restrict__ out_lens)
{
    int b = blockIdx.x;
    int cnt = 0;
    for (int s = threadIdx.x; s < SEQ; s += blockDim.x)
        cnt += (text[b*SEQ + s] != 0);
    for (int o = 16; o; o >>= 1) cnt += __shfl_down_sync(0xffffffffu, cnt, o);
    __shared__ int ws[4];
    if ((threadIdx.x & 31) == 0) ws[threadIdx.x >> 5] = cnt;
    __syncthreads();
    if (threadIdx.x == 0) {
        int t = ws[0] + ws[1] + ws[2] + ws[3];
        g_lens[b] = t;
        out_lens[b] = (float)t;
    }
}

// ---------------- fused embedding gather + input projection ----------------
#define AS_STRIDE 68   // 64 rows + pad
__global__ void __launch_bounds__(256)
inproj_kernel(const int* __restrict__ text, const float* __restrict__ emb,
              const float* __restrict__ W_f, const float* __restrict__ W_b,
              const float* __restrict__ b_f, const float* __restrict__ b_b)
{
    extern __shared__ float sm[];
    float* As = sm;                     // [128 k][AS_STRIDE]
    float* Bs = sm + 128*AS_STRIDE;     // [128 k][128 cols]

    const int nb = blockIdx.x, mb = blockIdx.y, d = blockIdx.z;
    const int tid = threadIdx.x;
    const int row0 = mb*64;
    const int col0 = nb*128;
    const float* W    = d ? W_b : W_f;
    const float* bias = d ? b_b : b_f;

    for (int i = tid; i < 64*128; i += 256) {
        int r = i >> 7, k = i & 127;
        int tok = text[row0 + r];
        As[k*AS_STRIDE + r] = emb[(size_t)tok*EMBD + k];
    }
    for (int i = tid; i < 128*128; i += 256) {
        int k = i >> 7, cc = i & 127;
        Bs[i] = W[(size_t)k*G4 + col0 + cc];
    }
    __syncthreads();

    const int ty = tid >> 5, tx = tid & 31;
    ull acc[8][2];
    #pragma unroll
    for (int j = 0; j < 8; j++) acc[j][0] = acc[j][1] = 0ULL;

    const ulonglong2* Bs2 = (const ulonglong2*)Bs;
    #pragma unroll 4
    for (int k = 0; k < 128; k++) {
        ulonglong2 bp = Bs2[k*32 + tx];
        float4 a0 = *(const float4*)(As + k*AS_STRIDE + ty*8);
        float4 a1 = *(const float4*)(As + k*AS_STRIDE + ty*8 + 4);
        ull ad;
        ad = pack2(a0.x); fma2(acc[0][0], ad, bp.x); fma2(acc[0][1], ad, bp.y);
        ad = pack2(a0.y); fma2(acc[1][0], ad, bp.x); fma2(acc[1][1], ad, bp.y);
        ad = pack2(a0.z); fma2(acc[2][0], ad, bp.x); fma2(acc[2][1], ad, bp.y);
        ad = pack2(a0.w); fma2(acc[3][0], ad, bp.x); fma2(acc[3][1], ad, bp.y);
        ad = pack2(a1.x); fma2(acc[4][0], ad, bp.x); fma2(acc[4][1], ad, bp.y);
        ad = pack2(a1.y); fma2(acc[5][0], ad, bp.x); fma2(acc[5][1], ad, bp.y);
        ad = pack2(a1.z); fma2(acc[6][0], ad, bp.x); fma2(acc[6][1], ad, bp.y);
        ad = pack2(a1.w); fma2(acc[7][0], ad, bp.x); fma2(acc[7][1], ad, bp.y);
    }
    float4 bb = *(const float4*)(bias + col0 + tx*4);
    float* outp = g_xz + (size_t)d*NROWS*G4;
    #pragma unroll
    for (int j = 0; j < 8; j++) {
        float2 lo = unpack2(acc[j][0]);
        float2 hi = unpack2(acc[j][1]);
        float4 v = make_float4(lo.x+bb.x, lo.y+bb.y, hi.x+bb.z, hi.y+bb.w);
        *(float4*)(outp + (size_t)(row0 + ty*8 + j)*G4 + col0 + tx*4) = v;
    }
}

// ---------------- LSTM scan: persistent-U, per-source dataflow barriers ----
// grid (8,8,2): x = hidden-group (cluster dim), y = batch-group, z = dir.
// 16 warps: warp = (kq 0..7 : 32-k slice, ch 0..1 : 64-col half).
// Slice kq of h is produced entirely by cluster rank kq, so each warp waits
// on its OWN 1KB per-source mbarrier full[buf][kq] instead of one 8KB global
// barrier: consumers start as soon as their slice lands; peer skew and the
// st.async drain overlap with other warps' FMA.
#define ZS_STRIDE 132
#define NTHR 512
__global__ void __cluster_dims__(8,1,1) __launch_bounds__(NTHR,1)
lstm_kernel(const float* __restrict__ Uf, const float* __restrict__ Ub)
{
    extern __shared__ float sm[];
    float* Us  = sm;                          // [256 k][128 lc]       131072 B
    ull*   hb2 = (ull*)(sm + 256*128);        // [2][256 k][4 bpair]    16384 B
    ull*   zs2 = hb2 + 2*256*4;               // [2][32 row][ZS_STRIDE] 67584 B
    ull*   mbs = zs2 + 2*32*ZS_STRIDE;        // full[2][8]               128 B

    const int c   = blockIdx.x;
    const int g   = blockIdx.y;
    const int d   = blockIdx.z;
    const int tid = threadIdx.x;
    const float* U = d ? Ub : Uf;

    const uint32_t hb2_u32 = smem_u32(hb2);
    const uint32_t mb_u32  = smem_u32(mbs);

    // U slice: local col lc = q*32+jj -> global col q*256 + c*32 + jj
    for (int i = tid; i < 256*128; i += NTHR) {
        int k = i >> 7, lc = i & 127;
        int q = lc >> 5, jj = lc & 31;
        Us[i] = U[(size_t)k*G4 + q*HID + c*32 + jj];
    }
    for (int i = tid; i < 256*4; i += NTHR) hb2[i] = 0ULL;   // h0 = 0 (buffer 0)
    if (tid < 16) {                      // full[buf=tid>>3][src=tid&7]
        uint32_t mb = mb_u32 + tid*8;
        mbar_init(mb, 1);
        mbar_expect_tx(mb, 1024);
    }
    __syncthreads();
    // mbarriers must be cluster-visible before any peer st.async
    asm volatile("barrier.cluster.arrive.aligned;" ::: "memory");
    asm volatile("barrier.cluster.wait.aligned;"   ::: "memory");

    // FMA-phase mapping: 16 warps
    const int w    = tid >> 5, lane = tid & 31;
    const int kq   = w >> 1;            // 32-k slice [kq*32, kq*32+32)
    const int ch   = w & 1;             // col half
    const int lc0  = ch*64 + lane*2;    // local col pair

    // gate-phase mapping (threads 0..255)
    const int b   = tid & 7;
    const int hid = (tid >> 3) & 31;
    const int bg  = g*8 + b;
    const bool gate_thr = (tid < 256);
    const float* xzb = g_xz + (size_t)d*NROWS*G4 + (size_t)bg*SEQ*G4 + c*32 + hid;
    float cstate = 0.f;

    int ph0 = 0, ph1 = 0;   // per-buffer phase counters (uniform across threads)

    for (int s = 0; s < SEQ; s++) {
        const int t = d ? (SEQ - 1 - s) : s;
        const int p = s & 1;

        // prefetch xz gate inputs (in flight across the wait + FMA phase)
        float xz0 = 0.f, xz1 = 0.f, xz2 = 0.f, xz3 = 0.f;
        if (gate_thr) {
            const float* xzr = xzb + (size_t)t*G4;
            xz0 = __ldg(xzr);
            xz1 = __ldg(xzr + 256);
            xz2 = __ldg(xzr + 512);
            xz3 = __ldg(xzr + 768);
        }

        // wait ONLY for this warp's source slice (step 0: zeroed buffer 0)
        if (s > 0) {
            uint32_t mb = mb_u32 + (p*8 + kq)*8;
            int phase = (p ? ph1 : ph0) & 1;
            mbar_wait(mb, (uint32_t)phase);
            // re-arm by one elected thread per slice; causally safe: next
            // arrivals require the peer to consume our step-s send first
            if (ch == 0 && lane == 0) mbar_expect_tx(mb, 1024);
        }
        if (p) ph1 += (s > 0); else ph0 += (s > 0);

        // ---- h @ U partial (this warp's 32-k slice, col pair) ----
        ull acc[4][2];
        #pragma unroll
        for (int pp = 0; pp < 4; pp++) acc[pp][0] = acc[pp][1] = 0ULL;

        const ull* hrow = hb2 + (size_t)p*1024 + (size_t)kq*32*4;
        const float* Uk = Us + kq*32*128 + lc0;
        #pragma unroll 4
        for (int kk = 0; kk < 32; kk++) {
            float2 u = *(const float2*)(Uk + kk*128);
            ull u0 = pack2(u.x), u1 = pack2(u.y);
            ulonglong2 hA = *(const ulonglong2*)(hrow + kk*4);
            ulonglong2 hB = *(const ulonglong2*)(hrow + kk*4 + 2);
            fma2(acc[0][0], hA.x, u0); fma2(acc[0][1], hA.x, u1);
            fma2(acc[1][0], hA.y, u0); fma2(acc[1][1], hA.y, u1);
            fma2(acc[2][0], hB.x, u0); fma2(acc[2][1], hB.x, u1);
            fma2(acc[3][0], hB.y, u0); fma2(acc[3][1], hB.y, u1);
        }
        ull* zrow = zs2 + (size_t)p*32*ZS_STRIDE;
        #pragma unroll
        for (int pp = 0; pp < 4; pp++) {
            *(ulonglong2*)(zrow + (size_t)(kq*4 + pp)*ZS_STRIDE + lc0) =
                make_ulonglong2(acc[pp][0], acc[pp][1]);
        }
        __syncthreads();

        // ---- gates (threads 0..255) ----
        if (gate_thr) {
            float zsum[4];
            #pragma unroll
            for (int q = 0; q < 4; q++) {
                float ssum = (q==0) ? xz0 : (q==1) ? xz1 : (q==2) ? xz2 : xz3;
                #pragma unroll
                for (int k2 = 0; k2 < 8; k2++) {
                    const float* zp = (const float*)(zrow + (size_t)(k2*4 + (b>>1))*ZS_STRIDE
                                                     + q*32 + hid) + (b & 1);
                    ssum += *zp;
                }
                zsum[q] = ssum;
            }
            cstate = sig_a(zsum[1])*cstate + sig_a(zsum[0])*tanh_a(zsum[2]);
            float hv = sig_a(zsum[3])*tanh_a(cstate);

            // both pair threads build the identical (even,odd) packed value;
            // even-b sends ranks 0..3, odd-b sends ranks 4..7 — sends FIRST,
            // g_h store after (send is on the cluster critical path)
            float hpart = __shfl_xor_sync(0xffffffffu, hv, 1);
            if (s < SEQ-1) {
                ull pairv = (b & 1) ? packab(hpart, hv) : packab(hv, hpart);
                uint32_t laddr = hb2_u32 +
                    (uint32_t)((((1 - p)*256 + c*32 + hid)*4 + (b >> 1)) * 8);
                uint32_t lmb = mb_u32 + ((1 - p)*8 + c)*8;   // dest slice = our rank
                const int r0 = (b & 1) * 4;
                #pragma unroll
                for (int rr = 0; rr < 4; rr++) {
                    uint32_t raddr, rmb;
                    asm volatile("mapa.shared::cluster.u32 %0, %1, %2;"
                                 : "=r"(raddr) : "r"(laddr), "r"(r0 + rr));
                    asm volatile("mapa.shared::cluster.u32 %0, %1, %2;"
                                 : "=r"(rmb) : "r"(lmb), "r"(r0 + rr));
                    asm volatile("st.async.shared::cluster.mbarrier::complete_tx::bytes.b64 "
                                 "[%0], %1, [%2];"
                                 :: "r"(raddr), "l"(pairv), "r"(rmb) : "memory");
                }
            }
            g_h[((size_t)bg*SEQ + t)*(2*HID) + d*HID + c*32 + hid] = hv;
        }
    }
}

// ---------------- logits = h @ W_d + b_d  (warp per row) -------------------
__global__ void __launch_bounds__(256)
logits_kernel(const float* __restrict__ Wd, const float* __restrict__ bd,
              float* __restrict__ out)
{
    __shared__ float Ws[2*HID*TAGS];
    const int tid = threadIdx.x;
    for (int i = tid; i < 2*HID*TAGS; i += 256) Ws[i] = Wd[i];
    __syncthreads();

    const int warp = tid >> 5, lane = tid & 31;
    const int row = blockIdx.x*8 + warp;
    const float* hr = g_h + (size_t)row*(2*HID);

    float a[TAGS];
    #pragma unroll
    for (int tg = 0; tg < TAGS; tg++) a[tg] = 0.f;
    for (int k = lane; k < 2*HID; k += 32) {
        float hv = hr[k];
        #pragma unroll
        for (int tg = 0; tg < TAGS; tg++) a[tg] = fmaf(hv, Ws[k*TAGS + tg], a[tg]);
    }
    #pragma unroll
    for (int tg = 0; tg < TAGS; tg++)
        for (int o = 16; o; o >>= 1) a[tg] += __shfl_down_sync(0xffffffffu, a[tg], o);
    if (lane == 0) {
        #pragma unroll
        for (int tg = 0; tg < TAGS; tg++)
            out[(size_t)row*TAGS + tg] = a[tg] + bd[tg];
    }
}

// ---------------- CRF -------------------------------------------------------
__global__ void crf_kernel(const int* __restrict__ labels, const float* __restrict__ trans,
                           const float* __restrict__ logits, float* __restrict__ out_ll)
{
    __shared__ float tr[TAGS*TAGS];
    __shared__ float alpha[TAGS];
    const int b = blockIdx.x;
    const int tid = threadIdx.x;

    for (int i = tid; i < TAGS*TAGS; i += 32) tr[i] = trans[i];
    const int len = g_lens[b];
    const float* lg = logits + (size_t)b*SEQ*TAGS;
    if (tid < TAGS) alpha[tid] = lg[tid];
    __syncwarp();

    for (int t = 1; t < len; t++) {
        float nv = 0.f;
        if (tid < TAGS) {
            float m = -1e30f;
            #pragma unroll
            for (int i = 0; i < TAGS; i++) m = fmaxf(m, alpha[i] + tr[i*TAGS + tid]);
            float s = 0.f;
            #pragma unroll
            for (int i = 0; i < TAGS; i++) s += __expf(alpha[i] + tr[i*TAGS + tid] - m);
            nv = m + __logf(s) + lg[t*TAGS + tid];
        }
        __syncwarp();
        if (tid < TAGS) alpha[tid] = nv;
        __syncwarp();
    }

    const int* lb = labels + b*SEQ;
    float sc = 0.f;
    for (int t = tid; t < len; t += 32)      sc += lg[t*TAGS + lb[t]];
    for (int t = tid; t + 1 < len; t += 32)  sc += tr[lb[t]*TAGS + lb[t+1]];
    for (int o = 16; o; o >>= 1) sc += __shfl_down_sync(0xffffffffu, sc, o);

    if (tid == 0) {
        float m = -1e30f;
        #pragma unroll
        for (int i = 0; i < TAGS; i++) m = fmaxf(m, alpha[i]);
        float s = 0.f;
        #pragma unroll
        for (int i = 0; i < TAGS; i++) s += __expf(alpha[i] - m);
        out_ll[b] = sc - (m + __logf(s));
    }
}

// ---------------- launch ----------------------------------------------------
extern "C" void kernel_launch(void* const* d_in, const int* in_sizes, int n_in,
                              void* d_out, int out_size)
{
    (void)in_sizes; (void)n_in; (void)out_size;
    const int*   text   = (const int*)  d_in[0];
    const int*   labels = (const int*)  d_in[1];
    const float* emb    = (const float*)d_in[2];
    const float* W_f    = (const float*)d_in[3];
    const float* U_f    = (const float*)d_in[4];
    const float* b_f    = (const float*)d_in[5];
    const float* W_b    = (const float*)d_in[6];
    const float* U_b    = (const float*)d_in[7];
    const float* b_b    = (const float*)d_in[8];
    const float* W_d    = (const float*)d_in[9];
    const float* b_d    = (const float*)d_in[10];
    const float* trans  = (const float*)d_in[11];
    float* out = (float*)d_out;

    const int gemm_smem = (128*AS_STRIDE + 128*128) * 4;                   // 100352
    const int lstm_smem = 256*128*4 + 2*256*4*8 + 2*32*ZS_STRIDE*8 + 128;  // 215168
    cudaFuncSetAttribute(inproj_kernel, cudaFuncAttributeMaxDynamicSharedMemorySize, gemm_smem);
    cudaFuncSetAttribute(lstm_kernel,   cudaFuncAttributeMaxDynamicSharedMemorySize, lstm_smem);

    lens_kernel<<<BATCH, 128>>>(text, out + LOGITS_N);

    dim3 ggrid(8, NROWS/64, 2);
    inproj_kernel<<<ggrid, 256, gemm_smem>>>(text, emb, W_f, W_b, b_f, b_b);

    // pad launch (idempotent) so the ncu capture slot lands on lstm_kernel
    lens_kernel<<<BATCH, 128>>>(text, out + LOGITS_N);

    dim3 lgrid(8, 8, 2);
    lstm_kernel<<<lgrid, NTHR, lstm_smem>>>(U_f, U_b);

    logits_kernel<<<NROWS/8, 256>>>(W_d, b_d, out);

    crf_kernel<<<BATCH, 32>>>(labels, trans, out, out + LOGITS_N + BATCH);
}